// round 4
// baseline (speedup 1.0000x reference)
#include <cuda_runtime.h>
#include <math.h>

// ---------------- problem constants ----------------
namespace {
constexpr int B_ = 4, C_ = 128, T_ = 1000, F_ = 65;
constexpr int H_ = 4, E_ = 8, DH = 32;
constexpr int T1 = 199;          // pooled length per sign: (1000-10)/5+1
constexpr int TC = 398;          // 2*T1
constexpr int EF = E_ * F_;      // 520
constexpr int DF = DH * F_;      // 2080
constexpr float EPS = 1e-5f;
constexpr float QSCALE = 0.04385290096535146f;  // 1/sqrt(520)
}

// ---------------- scratch (no-alloc rule: __device__ globals) ----------------
__device__ float d_cond[(size_t)B_ * C_ * TC * F_];   // [b,c,tc,f]      ~53 MB
__device__ float d_Qf [(size_t)H_ * B_ * T_ * EF];    // [h,b,t, e*F+f]  ~33 MB
__device__ float d_Kf [(size_t)H_ * B_ * TC * EF];    //                 ~13 MB
__device__ float d_Vf [(size_t)H_ * B_ * TC * DF];    //                 ~53 MB
__device__ float d_P  [(size_t)H_ * B_ * T_ * TC];    // scores/probs    ~25 MB
__device__ float d_O  [(size_t)H_ * B_ * T_ * DF];    // attn out        ~133 MB

// ---------------- 1) avg-pool along T + signed concat ----------------
__global__ void pool_kernel(const float* __restrict__ pos, const float* __restrict__ neg) {
    int idx = blockIdx.x * blockDim.x + threadIdx.x;
    constexpr int total = B_ * C_ * TC * F_;
    if (idx >= total) return;
    int f  = idx % F_;
    int r  = idx / F_;
    int tc = r % TC;  r /= TC;
    int c  = r % C_;
    int b  = r / C_;
    const float* src; float sg; int t0;
    if (tc < T1) { src = pos; sg =  0.1f; t0 = tc * 5; }
    else         { src = neg; sg = -0.1f; t0 = (tc - T1) * 5; }
    const float* p = src + ((size_t)(b * C_ + c) * T_ + t0) * F_ + f;
    float s = 0.f;
#pragma unroll
    for (int k = 0; k < 10; k++) s += p[(size_t)k * F_];
    d_cond[idx] = s * sg;
}

// ---------------- 2) conv1x1 + PReLU + LN(group, F) branch kernels ----------------
// One block per (b, t). Y[OC,65] = W[OC,128] @ X[128,65]; per-thread 4oc x 5f tile.
// MODE: 0=Q(batch->Qf, *QSCALE)  1=K(cond->Kf)  2=V(cond->Vf)  3=proj(d_O->out)
template <int OC, int GRP, int MODE>
__global__ void __launch_bounds__(OC * 13 / 4)
conv_ln_kernel(const float* __restrict__ xin, const float* __restrict__ W,
               const float* __restrict__ bias, const float* __restrict__ alpha,
               const float* __restrict__ gamma, const float* __restrict__ beta,
               float* __restrict__ outp) {
    constexpr int Tx = (MODE == 1 || MODE == 2) ? TC : T_;
    constexpr int WS = 130;                 // padded W stride (bank-conflict-free)
    constexpr int NTHR = OC * 13 / 4;
    extern __shared__ float sm[];
    float* xs = sm;                         // C_*F_ = 8320 floats
    float* ws = sm + C_ * F_;               // OC*WS floats
    __shared__ float s_sum[OC / GRP], s_sq[OC / GRP];

    int bid = blockIdx.x;
    int b = bid / Tx, t = bid % Tx;
    int tid = threadIdx.x;

    // load X tile
    for (int i = tid; i < C_ * F_; i += NTHR) {
        int c = i / F_, f = i - c * F_;
        float v;
        if (MODE == 0) {
            v = xin[((size_t)(b * C_ + c) * T_ + t) * F_ + f];
        } else if (MODE == 3) {
            int h = c / DH, dd = c - h * DH;
            v = d_O[((size_t)(h * B_ + b) * T_ + t) * DF + dd * F_ + f];
        } else {
            v = d_cond[((size_t)(b * C_ + c) * TC + t) * F_ + f];
        }
        xs[i] = v;
    }
    // load W (row-padded)
    for (int i = tid; i < OC * C_; i += NTHR) ws[(i >> 7) * WS + (i & 127)] = W[i];
    if (tid < OC / GRP) { s_sum[tid] = 0.f; s_sq[tid] = 0.f; }
    __syncthreads();

    int ocg = tid / 13, fg = tid - ocg * 13;
    int oc0 = ocg * 4, f0 = fg * 5;

    float acc[4][5];
#pragma unroll
    for (int i = 0; i < 4; i++) {
        float bv = bias[oc0 + i];
#pragma unroll
        for (int j = 0; j < 5; j++) acc[i][j] = bv;
    }
    for (int c = 0; c < C_; c++) {
        float xv[5];
#pragma unroll
        for (int j = 0; j < 5; j++) xv[j] = xs[c * F_ + f0 + j];
#pragma unroll
        for (int i = 0; i < 4; i++) {
            float wv = ws[(oc0 + i) * WS + c];
#pragma unroll
            for (int j = 0; j < 5; j++) acc[i][j] = fmaf(wv, xv[j], acc[i][j]);
        }
    }

    // PReLU + LN partial stats (thread tile lies in exactly one group)
    int g = oc0 / GRP;
    float a = alpha[g];
    float ps = 0.f, pq = 0.f;
#pragma unroll
    for (int i = 0; i < 4; i++)
#pragma unroll
        for (int j = 0; j < 5; j++) {
            float v = acc[i][j];
            v = (v >= 0.f) ? v : a * v;
            acc[i][j] = v;
            ps += v; pq += v * v;
        }
    atomicAdd(&s_sum[g], ps);
    atomicAdd(&s_sq[g], pq);
    __syncthreads();

    const float invn = 1.f / (float)(GRP * F_);
    float mu  = s_sum[g] * invn;
    float var = s_sq[g] * invn - mu * mu;
    float rinv = rsqrtf(var + EPS);
    const float sc = (MODE == 0) ? QSCALE : 1.0f;

#pragma unroll
    for (int i = 0; i < 4; i++) {
        int oc = oc0 + i;
#pragma unroll
        for (int j = 0; j < 5; j++) {
            int f = f0 + j;
            float v = (acc[i][j] - mu) * rinv * gamma[oc * F_ + f] + beta[oc * F_ + f];
            v *= sc;
            if (MODE == 0)
                d_Qf[((size_t)((oc >> 3) * B_ + b) * T_ + t) * EF + (oc & 7) * F_ + f] = v;
            else if (MODE == 1)
                d_Kf[((size_t)((oc >> 3) * B_ + b) * TC + t) * EF + (oc & 7) * F_ + f] = v;
            else if (MODE == 2)
                d_Vf[((size_t)((oc >> 5) * B_ + b) * TC + t) * DF + (oc & 31) * F_ + f] = v;
            else
                outp[((size_t)(b * C_ + oc) * T_ + t) * F_ + f] = v;
        }
    }
}

// ---------------- 3) scores: S = Qf @ Kf^T  (NT, per (h,b)) ----------------
__global__ void __launch_bounds__(256) gemm_nt_kernel() {
    __shared__ float As[8][64];
    __shared__ float Bs[8][64];
    int z = blockIdx.z;
    const float* A  = d_Qf + (size_t)z * T_ * EF;
    const float* Bm = d_Kf + (size_t)z * TC * EF;
    float* Cp       = d_P  + (size_t)z * T_ * TC;
    int mBase = blockIdx.y * 64, nBase = blockIdx.x * 64;
    int tid = threadIdx.x;
    int tx = tid & 15, ty = tid >> 4;
    int m0 = ty * 4, n0 = tx * 4;
    float acc[4][4];
#pragma unroll
    for (int i = 0; i < 4; i++)
#pragma unroll
        for (int j = 0; j < 4; j++) acc[i][j] = 0.f;

    bool isB = tid >= 128;
    int lt = tid & 127, lr = lt >> 1, lq = lt & 1;

    for (int k0 = 0; k0 < EF; k0 += 8) {
        float4 v = make_float4(0.f, 0.f, 0.f, 0.f);
        if (!isB) { int r = mBase + lr; if (r < T_) v = *(const float4*)(A  + (size_t)r * EF + k0 + lq * 4); }
        else      { int r = nBase + lr; if (r < TC) v = *(const float4*)(Bm + (size_t)r * EF + k0 + lq * 4); }
        __syncthreads();
        float* S = isB ? &Bs[0][0] : &As[0][0];
        S[(lq * 4 + 0) * 64 + lr] = v.x;
        S[(lq * 4 + 1) * 64 + lr] = v.y;
        S[(lq * 4 + 2) * 64 + lr] = v.z;
        S[(lq * 4 + 3) * 64 + lr] = v.w;
        __syncthreads();
#pragma unroll
        for (int kk = 0; kk < 8; kk++) {
            float4 av = *(const float4*)&As[kk][m0];
            float4 bv = *(const float4*)&Bs[kk][n0];
            float aa[4] = {av.x, av.y, av.z, av.w};
            float bb[4] = {bv.x, bv.y, bv.z, bv.w};
#pragma unroll
            for (int i = 0; i < 4; i++)
#pragma unroll
                for (int j = 0; j < 4; j++) acc[i][j] = fmaf(aa[i], bb[j], acc[i][j]);
        }
    }
#pragma unroll
    for (int i = 0; i < 4; i++) {
        int m = mBase + m0 + i;
        if (m >= T_) continue;
#pragma unroll
        for (int j = 0; j < 4; j++) {
            int n = nBase + n0 + j;
            if (n < TC) Cp[(size_t)m * TC + n] = acc[i][j];
        }
    }
}

// ---------------- 4) softmax over s (len 398), in place on d_P ----------------
__global__ void __launch_bounds__(128) softmax_kernel() {
    size_t row = blockIdx.x;
    float* p = d_P + row * TC;
    int tid = threadIdx.x;
    float v[4];
    int cnt = 0;
    float mx = -3.4e38f;
    for (int i = tid; i < TC; i += 128) { float x = p[i]; v[cnt++] = x; mx = fmaxf(mx, x); }
    __shared__ float smax[4], ssum[4];
#pragma unroll
    for (int o = 16; o > 0; o >>= 1) mx = fmaxf(mx, __shfl_xor_sync(0xffffffffu, mx, o));
    if ((tid & 31) == 0) smax[tid >> 5] = mx;
    __syncthreads();
    mx = fmaxf(fmaxf(smax[0], smax[1]), fmaxf(smax[2], smax[3]));
    float s = 0.f;
    for (int k = 0; k < cnt; k++) { float e = __expf(v[k] - mx); v[k] = e; s += e; }
#pragma unroll
    for (int o = 16; o > 0; o >>= 1) s += __shfl_xor_sync(0xffffffffu, s, o);
    if ((tid & 31) == 0) ssum[tid >> 5] = s;
    __syncthreads();
    s = ssum[0] + ssum[1] + ssum[2] + ssum[3];
    float inv = 1.f / s;
    cnt = 0;
    for (int i = tid; i < TC; i += 128) p[i] = v[cnt++] * inv;
}

// ---------------- 5) out: O = P @ Vf  (NN, per (h,b)) ----------------
__global__ void __launch_bounds__(256) gemm_nn_kernel() {
    __shared__ float As[8][64];
    __shared__ float Bs[8][64];
    int z = blockIdx.z;
    const float* A  = d_P  + (size_t)z * T_ * TC;
    const float* Bm = d_Vf + (size_t)z * TC * DF;
    float* Cp       = d_O  + (size_t)z * T_ * DF;
    int mBase = blockIdx.y * 64, nBase = blockIdx.x * 64;
    int tid = threadIdx.x;
    int tx = tid & 15, ty = tid >> 4;
    int m0 = ty * 4, n0 = tx * 4;
    float acc[4][4];
#pragma unroll
    for (int i = 0; i < 4; i++)
#pragma unroll
        for (int j = 0; j < 4; j++) acc[i][j] = 0.f;

    int alr = tid >> 2, alq = tid & 3;   // A loader: row, k-pair
    int bkk = tid >> 5, bnq = tid & 31;  // B loader: k row, n-pair

    for (int k0 = 0; k0 < TC; k0 += 8) {
        float a0 = 0.f, a1 = 0.f, b0 = 0.f, b1 = 0.f;
        int ar = mBase + alr, ak = k0 + alq * 2;
        if (ar < T_) {
            if (ak     < TC) a0 = A[(size_t)ar * TC + ak];
            if (ak + 1 < TC) a1 = A[(size_t)ar * TC + ak + 1];
        }
        int bk = k0 + bkk, bn = nBase + bnq * 2;
        if (bk < TC) {
            if (bn     < DF) b0 = Bm[(size_t)bk * DF + bn];
            if (bn + 1 < DF) b1 = Bm[(size_t)bk * DF + bn + 1];
        }
        __syncthreads();
        As[alq * 2    ][alr] = a0;
        As[alq * 2 + 1][alr] = a1;
        Bs[bkk][bnq * 2    ] = b0;
        Bs[bkk][bnq * 2 + 1] = b1;
        __syncthreads();
#pragma unroll
        for (int kk = 0; kk < 8; kk++) {
            float4 av = *(const float4*)&As[kk][m0];
            float4 bv = *(const float4*)&Bs[kk][n0];
            float aa[4] = {av.x, av.y, av.z, av.w};
            float bb[4] = {bv.x, bv.y, bv.z, bv.w};
#pragma unroll
            for (int i = 0; i < 4; i++)
#pragma unroll
                for (int j = 0; j < 4; j++) acc[i][j] = fmaf(aa[i], bb[j], acc[i][j]);
        }
    }
#pragma unroll
    for (int i = 0; i < 4; i++) {
        int m = mBase + m0 + i;
        if (m >= T_) continue;
#pragma unroll
        for (int j = 0; j < 4; j++) {
            int n = nBase + n0 + j;
            if (n < DF) Cp[(size_t)m * DF + n] = acc[i][j];
        }
    }
}

// ---------------- launch ----------------
extern "C" void kernel_launch(void* const* d_in, const int* in_sizes, int n_in,
                              void* d_out, int out_size) {
    (void)in_sizes; (void)n_in; (void)out_size;
    const float* batch = (const float*)d_in[0];
    const float* pos   = (const float*)d_in[1];
    const float* neg   = (const float*)d_in[2];
    const float* WQ  = (const float*)d_in[3];
    const float* bQ  = (const float*)d_in[4];
    const float* aQ  = (const float*)d_in[5];
    const float* gQ  = (const float*)d_in[6];
    const float* btQ = (const float*)d_in[7];
    const float* WK  = (const float*)d_in[8];
    const float* bK  = (const float*)d_in[9];
    const float* aK  = (const float*)d_in[10];
    const float* gK  = (const float*)d_in[11];
    const float* btK = (const float*)d_in[12];
    const float* WV  = (const float*)d_in[13];
    const float* bV  = (const float*)d_in[14];
    const float* aV  = (const float*)d_in[15];
    const float* gV  = (const float*)d_in[16];
    const float* btV = (const float*)d_in[17];
    const float* Wp  = (const float*)d_in[18];
    const float* bp  = (const float*)d_in[19];
    const float* ap  = (const float*)d_in[20];
    const float* gp  = (const float*)d_in[21];
    const float* btp = (const float*)d_in[22];
    float* out = (float*)d_out;

    const size_t smQK = (size_t)(C_ * F_ + 32  * 130) * sizeof(float);  // 49,920 B
    const size_t smVP = (size_t)(C_ * F_ + 128 * 130) * sizeof(float);  // 99,840 B
    cudaFuncSetAttribute(conv_ln_kernel<32, 8, 0>,    cudaFuncAttributeMaxDynamicSharedMemorySize, (int)smQK);
    cudaFuncSetAttribute(conv_ln_kernel<32, 8, 1>,    cudaFuncAttributeMaxDynamicSharedMemorySize, (int)smQK);
    cudaFuncSetAttribute(conv_ln_kernel<128, 32, 2>,  cudaFuncAttributeMaxDynamicSharedMemorySize, (int)smVP);
    cudaFuncSetAttribute(conv_ln_kernel<128, 128, 3>, cudaFuncAttributeMaxDynamicSharedMemorySize, (int)smVP);

    {   // pooled signed cond
        int total = B_ * C_ * TC * F_;
        pool_kernel<<<(total + 255) / 256, 256>>>(pos, neg);
    }
    // Q / K / V branches
    conv_ln_kernel<32, 8, 0><<<B_ * T_, 104, smQK>>>(batch, WQ, bQ, aQ, gQ, btQ, nullptr);
    conv_ln_kernel<32, 8, 1><<<B_ * TC, 104, smQK>>>(nullptr, WK, bK, aK, gK, btK, nullptr);
    conv_ln_kernel<128, 32, 2><<<B_ * TC, 416, smVP>>>(nullptr, WV, bV, aV, gV, btV, nullptr);
    {   // scores
        dim3 g((TC + 63) / 64, (T_ + 63) / 64, H_ * B_);
        gemm_nt_kernel<<<g, 256>>>();
    }
    softmax_kernel<<<H_ * B_ * T_, 128>>>();
    {   // attention output
        dim3 g((DF + 63) / 64, (T_ + 63) / 64, H_ * B_);
        gemm_nn_kernel<<<g, 256>>>();
    }
    // concat projection + LN -> final output
    conv_ln_kernel<128, 128, 3><<<B_ * T_, 416, smVP>>>(nullptr, Wp, bp, ap, gp, btp, out);
}

// round 7
// speedup vs baseline: 1.5267x; 1.5267x over previous
#include <cuda_runtime.h>
#include <cuda_bf16.h>
#include <math.h>
#include <stdint.h>

// ---------------- problem constants ----------------
namespace {
constexpr int B_ = 4, C_ = 128, T_ = 1000, F_ = 65;
constexpr int H_ = 4, E_ = 8, DH = 32;
constexpr int T1 = 199;          // pooled length per sign
constexpr int TC = 398;          // 2*T1
constexpr int EF = E_ * F_;      // 520
constexpr int DF = DH * F_;      // 2080
constexpr int PLD = 416;         // padded K-stride for P / VfT (13*32)
constexpr float EPS = 1e-5f;
constexpr float QSCALE = 0.04385290096535146f;  // 1/sqrt(520)
}

// ---------------- scratch (__device__ globals; no-alloc rule) ----------------
__device__ __align__(16) float d_cond[(size_t)B_ * C_ * TC * F_];
__device__ __align__(16) float d_Qf [(size_t)H_ * B_ * T_ * EF];   // [z, t, ef]
__device__ __align__(16) float d_Kf [(size_t)H_ * B_ * TC * EF];   // [z, tc, ef]
__device__ __align__(16) float d_Vf [(size_t)H_ * B_ * TC * DF];   // [z, tc, n]
__device__ __align__(16) float d_VfT[(size_t)H_ * B_ * DF * PLD];  // [z, n, tc(pad0)]
__device__ __align__(16) float d_P  [(size_t)H_ * B_ * T_ * PLD];  // [z, t, tc(pad)]
__device__ __align__(16) float d_O  [(size_t)H_ * B_ * T_ * DF];   // [z, t, n]

// ---------------- helpers ----------------
__device__ __forceinline__ uint32_t smem_u32(const void* p) {
    uint32_t a;
    asm("{ .reg .u64 t; cvta.to.shared.u64 t, %1; cvt.u32.u64 %0, t; }" : "=r"(a) : "l"(p));
    return a;
}
__device__ __forceinline__ uint32_t pk2(float lo, float hi) {
    // result: low 16 bits = bf16(lo), high 16 bits = bf16(hi)  (memory order lo, hi)
    uint32_t r;
    asm("cvt.rn.bf16x2.f32 %0, %1, %2;" : "=r"(r) : "f"(hi), "f"(lo));
    return r;
}
__device__ __forceinline__ float bfhi(float x) {
    return __bfloat162float(__float2bfloat16(x));
}
__device__ __forceinline__ void ldsm4(uint32_t& r0, uint32_t& r1, uint32_t& r2, uint32_t& r3,
                                      uint32_t addr) {
    asm volatile("ldmatrix.sync.aligned.m8n8.x4.shared.b16 {%0,%1,%2,%3}, [%4];"
                 : "=r"(r0), "=r"(r1), "=r"(r2), "=r"(r3) : "r"(addr));
}
__device__ __forceinline__ void mma16816(float* c, const uint32_t* a, uint32_t b0, uint32_t b1) {
    asm volatile(
        "mma.sync.aligned.m16n8k16.row.col.f32.bf16.bf16.f32 "
        "{%0,%1,%2,%3}, {%4,%5,%6,%7}, {%8,%9}, {%0,%1,%2,%3};"
        : "+f"(c[0]), "+f"(c[1]), "+f"(c[2]), "+f"(c[3])
        : "r"(a[0]), "r"(a[1]), "r"(a[2]), "r"(a[3]), "r"(b0), "r"(b1));
}

// ---------------- 1) avg-pool along T + signed concat ----------------
__global__ void pool_kernel(const float* __restrict__ pos, const float* __restrict__ neg) {
    int idx = blockIdx.x * blockDim.x + threadIdx.x;
    constexpr int total = B_ * C_ * TC * F_;
    if (idx >= total) return;
    int f  = idx % F_;
    int r  = idx / F_;
    int tc = r % TC;  r /= TC;
    int c  = r % C_;
    int b  = r / C_;
    const float* src; float sg; int t0;
    if (tc < T1) { src = pos; sg =  0.1f; t0 = tc * 5; }
    else         { src = neg; sg = -0.1f; t0 = (tc - T1) * 5; }
    const float* p = src + ((size_t)(b * C_ + c) * T_ + t0) * F_ + f;
    float s = 0.f;
#pragma unroll
    for (int k = 0; k < 10; k++) s += p[(size_t)k * F_];
    d_cond[idx] = s * sg;
}

// ---------------- 2) conv1x1 + PReLU + LN branch kernels ----------------
// One block per (b, t). Per-thread OCT x 5 register tile.
// MODE: 0=Q(batch->Qf, *QSCALE)  1=K(cond->Kf)  2=V(cond->Vf)  3=proj(d_O->out)
template <int OC, int GRP, int MODE, int OCT>
__global__ void __launch_bounds__((OC / OCT) * 13)
conv_ln_kernel(const float* __restrict__ xin, const float* __restrict__ W,
               const float* __restrict__ bias, const float* __restrict__ alpha,
               const float* __restrict__ gamma, const float* __restrict__ beta,
               float* __restrict__ outp) {
    constexpr int Tx = (MODE == 1 || MODE == 2) ? TC : T_;
    constexpr int WS = 130;
    constexpr int NTHR = (OC / OCT) * 13;
    extern __shared__ float sm[];
    float* xs = sm;                        // C_*F_
    float* ws = sm + C_ * F_;              // OC*WS
    __shared__ float s_sum[OC / GRP], s_sq[OC / GRP];

    int bid = blockIdx.x;
    int b = bid / Tx, t = bid % Tx;
    int tid = threadIdx.x;

    for (int i = tid; i < C_ * F_; i += NTHR) {
        int c = i / F_, f = i - c * F_;
        float v;
        if (MODE == 0) {
            v = xin[((size_t)(b * C_ + c) * T_ + t) * F_ + f];
        } else if (MODE == 3) {
            int h = c / DH, dd = c - h * DH;
            v = d_O[((size_t)(h * B_ + b) * T_ + t) * DF + dd * F_ + f];
        } else {
            v = d_cond[((size_t)(b * C_ + c) * TC + t) * F_ + f];
        }
        xs[i] = v;
    }
    for (int i = tid; i < OC * C_; i += NTHR) ws[(i >> 7) * WS + (i & 127)] = W[i];
    if (tid < OC / GRP) { s_sum[tid] = 0.f; s_sq[tid] = 0.f; }
    __syncthreads();

    int ocg = tid / 13, fg = tid - ocg * 13;
    int oc0 = ocg * OCT, f0 = fg * 5;

    float acc[OCT][5];
#pragma unroll
    for (int i = 0; i < OCT; i++) {
        float bv = bias[oc0 + i];
#pragma unroll
        for (int j = 0; j < 5; j++) acc[i][j] = bv;
    }
    for (int c = 0; c < C_; c++) {
        float xv[5];
#pragma unroll
        for (int j = 0; j < 5; j++) xv[j] = xs[c * F_ + f0 + j];
#pragma unroll
        for (int i = 0; i < OCT; i++) {
            float wv = ws[(oc0 + i) * WS + c];
#pragma unroll
            for (int j = 0; j < 5; j++) acc[i][j] = fmaf(wv, xv[j], acc[i][j]);
        }
    }

    int g = oc0 / GRP;
    float a = alpha[g];
    float ps = 0.f, pq = 0.f;
#pragma unroll
    for (int i = 0; i < OCT; i++)
#pragma unroll
        for (int j = 0; j < 5; j++) {
            float v = acc[i][j];
            v = (v >= 0.f) ? v : a * v;
            acc[i][j] = v;
            ps += v; pq += v * v;
        }
    atomicAdd(&s_sum[g], ps);
    atomicAdd(&s_sq[g], pq);
    __syncthreads();

    const float invn = 1.f / (float)(GRP * F_);
    float mu  = s_sum[g] * invn;
    float var = s_sq[g] * invn - mu * mu;
    float rinv = rsqrtf(var + EPS);
    const float sc = (MODE == 0) ? QSCALE : 1.0f;

#pragma unroll
    for (int i = 0; i < OCT; i++) {
        int oc = oc0 + i;
#pragma unroll
        for (int j = 0; j < 5; j++) {
            int f = f0 + j;
            float v = (acc[i][j] - mu) * rinv * gamma[oc * F_ + f] + beta[oc * F_ + f];
            v *= sc;
            if (MODE == 0)
                d_Qf[((size_t)((oc >> 3) * B_ + b) * T_ + t) * EF + (oc & 7) * F_ + f] = v;
            else if (MODE == 1)
                d_Kf[((size_t)((oc >> 3) * B_ + b) * TC + t) * EF + (oc & 7) * F_ + f] = v;
            else if (MODE == 2)
                d_Vf[((size_t)((oc >> 5) * B_ + b) * TC + t) * DF + (oc & 31) * F_ + f] = v;
            else
                outp[((size_t)(b * C_ + oc) * T_ + t) * F_ + f] = v;
        }
    }
}

// ---------------- 3) transpose Vf [z,tc,n] -> VfT [z,n,tc(pad 416, zeros)] ----------------
__global__ void transpose_v_kernel() {
    __shared__ float tile[32][33];
    int z = blockIdx.z;
    int n0 = blockIdx.x * 32, t0 = blockIdx.y * 32;
    int tx = threadIdx.x, ty = threadIdx.y;   // (32, 8)
#pragma unroll
    for (int i = ty; i < 32; i += 8) {
        int t = t0 + i, n = n0 + tx;
        float v = 0.f;
        if (t < TC && n < DF) v = d_Vf[((size_t)z * TC + t) * DF + n];
        tile[i][tx] = v;
    }
    __syncthreads();
#pragma unroll
    for (int i = ty; i < 32; i += 8) {
        int n = n0 + i, t = t0 + tx;
        if (n < DF) d_VfT[((size_t)z * DF + n) * PLD + t] = tile[tx][i];
    }
}

// ---------------- 4) bf16-split tensor-core GEMM: C[M,N] = A[M,K] * B[N,K]^T ----------------
// 3x bf16 passes (hi*hi + hi*lo + lo*hi), fp32 accumulate. BM=BN=128, BK=32.
// 8 warps as 4(m) x 2(n); each warp 32x64 via m16n8k16 tiles.
__global__ void __launch_bounds__(256)
mma_gemm(const float* __restrict__ A, const float* __restrict__ B, float* __restrict__ C,
         int M, int NrowsB, int Kvalid, int Kchunks,
         int lda, int ldb, int ldc,
         long long sAz, long long sBz, long long sCz, int writeN) {
    extern __shared__ __align__(16) char smc[];
    uint32_t sb = smem_u32(smc);
    constexpr uint32_t TSB = 128u * 40u * 2u;           // 10240 B per tile
    // stage layout: [AH][AL][BH][BL], two stages

    int tid = threadIdx.x, lane = tid & 31, wid = tid >> 5;
    int wm = wid & 3, wn = wid >> 2;
    int z = blockIdx.z;
    const float* Az = A + sAz * z;
    const float* Bz = B + sBz * z;
    float* Cz = C + sCz * z;
    int mBase = blockIdx.y * 128, nBase = blockIdx.x * 128;

    float acc[2][8][4];
#pragma unroll
    for (int i = 0; i < 2; i++)
#pragma unroll
        for (int j = 0; j < 8; j++)
#pragma unroll
            for (int k = 0; k < 4; k++) acc[i][j][k] = 0.f;

    const float4 f4z = make_float4(0.f, 0.f, 0.f, 0.f);
    float4 ra[4], rb[4];

    auto ldg = [&](int c) {
        int k0 = c * 32;
#pragma unroll
        for (int i = 0; i < 4; i++) {
            int idx = i * 256 + tid;
            int r = idx >> 3, gk = k0 + ((idx & 7) << 2);
            int gra = mBase + r;
            ra[i] = (gra < M && gk < Kvalid) ? *(const float4*)(Az + (size_t)gra * lda + gk) : f4z;
            int grb = nBase + r;
            rb[i] = (grb < NrowsB && gk < Kvalid) ? *(const float4*)(Bz + (size_t)grb * ldb + gk) : f4z;
        }
    };
    auto sts = [&](int s) {
        char* st = smc + (size_t)s * 4 * TSB;
#pragma unroll
        for (int i = 0; i < 4; i++) {
            int idx = i * 256 + tid;
            int r = idx >> 3, k = (idx & 7) << 2;
            uint32_t off = (uint32_t)(r * 80 + k * 2);
            float4 v = ra[i];
            float hx = bfhi(v.x), hy = bfhi(v.y), hz = bfhi(v.z), hw = bfhi(v.w);
            uint2 Hc = make_uint2(pk2(hx, hy), pk2(hz, hw));
            uint2 Lc = make_uint2(pk2(v.x - hx, v.y - hy), pk2(v.z - hz, v.w - hw));
            *(uint2*)(st + off)        = Hc;
            *(uint2*)(st + TSB + off)  = Lc;
            v = rb[i];
            hx = bfhi(v.x); hy = bfhi(v.y); hz = bfhi(v.z); hw = bfhi(v.w);
            Hc = make_uint2(pk2(hx, hy), pk2(hz, hw));
            Lc = make_uint2(pk2(v.x - hx, v.y - hy), pk2(v.z - hz, v.w - hw));
            *(uint2*)(st + 2 * TSB + off) = Hc;
            *(uint2*)(st + 3 * TSB + off) = Lc;
        }
    };

    uint32_t aRow = (uint32_t)((wm * 32 + (lane & 15)) * 80 + ((lane >> 4) << 4));
    uint32_t bRow = (uint32_t)((wn * 64 + (lane & 15)) * 80 + ((lane >> 4) << 4));

    auto compute = [&](int s) {
        uint32_t st = sb + (uint32_t)s * 4 * TSB;
#pragma unroll
        for (int ks = 0; ks < 2; ks++) {
            uint32_t ah[2][4], al[2][4];
#pragma unroll
            for (int mi = 0; mi < 2; mi++) {
                uint32_t ad = st + aRow + (uint32_t)(mi * 1280 + ks * 32);
                ldsm4(ah[mi][0], ah[mi][1], ah[mi][2], ah[mi][3], ad);
                ldsm4(al[mi][0], al[mi][1], al[mi][2], al[mi][3], ad + TSB);
            }
#pragma unroll
            for (int j = 0; j < 4; j++) {
                uint32_t bd = st + 2 * TSB + bRow + (uint32_t)(j * 1280 + ks * 32);
                uint32_t h0, h1, h2, h3, l0, l1, l2, l3;
                ldsm4(h0, h1, h2, h3, bd);
                ldsm4(l0, l1, l2, l3, bd + TSB);
#pragma unroll
                for (int mi = 0; mi < 2; mi++) {
                    mma16816(acc[mi][2 * j],     ah[mi], h0, h2);
                    mma16816(acc[mi][2 * j + 1], ah[mi], h1, h3);
                    mma16816(acc[mi][2 * j],     ah[mi], l0, l2);
                    mma16816(acc[mi][2 * j + 1], ah[mi], l1, l3);
                    mma16816(acc[mi][2 * j],     al[mi], h0, h2);
                    mma16816(acc[mi][2 * j + 1], al[mi], h1, h3);
                }
            }
        }
    };

    ldg(0);
    sts(0);
    __syncthreads();
    for (int c = 0; c < Kchunks; c++) {
        bool nxt = (c + 1 < Kchunks);
        if (nxt) ldg(c + 1);
        compute(c & 1);
        if (nxt) {
            sts((c + 1) & 1);
            __syncthreads();
        }
    }

    // epilogue
#pragma unroll
    for (int mi = 0; mi < 2; mi++) {
#pragma unroll
        for (int ni = 0; ni < 8; ni++) {
            int r0 = mBase + wm * 32 + mi * 16 + (lane >> 2);
            int col = nBase + wn * 64 + ni * 8 + ((lane & 3) << 1);
            if (col < writeN) {
                if (r0 < M) {
                    float2 v = make_float2(acc[mi][ni][0], acc[mi][ni][1]);
                    *(float2*)(Cz + (size_t)r0 * ldc + col) = v;
                }
                if (r0 + 8 < M) {
                    float2 v = make_float2(acc[mi][ni][2], acc[mi][ni][3]);
                    *(float2*)(Cz + (size_t)(r0 + 8) * ldc + col) = v;
                }
            }
        }
    }
}

// ---------------- 5) softmax over tc (len 398), in place on d_P (ld 416) ----------------
__global__ void __launch_bounds__(128) softmax_kernel() {
    size_t row = blockIdx.x;
    float* p = d_P + row * PLD;
    int tid = threadIdx.x;
    float v[4];
    int cnt = 0;
    float mx = -3.4e38f;
    for (int i = tid; i < TC; i += 128) { float x = p[i]; v[cnt++] = x; mx = fmaxf(mx, x); }
    __shared__ float smax[4], ssum[4];
#pragma unroll
    for (int o = 16; o > 0; o >>= 1) mx = fmaxf(mx, __shfl_xor_sync(0xffffffffu, mx, o));
    if ((tid & 31) == 0) smax[tid >> 5] = mx;
    __syncthreads();
    mx = fmaxf(fmaxf(smax[0], smax[1]), fmaxf(smax[2], smax[3]));
    float s = 0.f;
    for (int k = 0; k < cnt; k++) { float e = __expf(v[k] - mx); v[k] = e; s += e; }
#pragma unroll
    for (int o = 16; o > 0; o >>= 1) s += __shfl_xor_sync(0xffffffffu, s, o);
    if ((tid & 31) == 0) ssum[tid >> 5] = s;
    __syncthreads();
    s = ssum[0] + ssum[1] + ssum[2] + ssum[3];
    float inv = 1.f / s;
    cnt = 0;
    for (int i = tid; i < TC; i += 128) p[i] = v[cnt++] * inv;
}

// ---------------- launch ----------------
extern "C" void kernel_launch(void* const* d_in, const int* in_sizes, int n_in,
                              void* d_out, int out_size) {
    (void)in_sizes; (void)n_in; (void)out_size;
    const float* batch = (const float*)d_in[0];
    const float* pos   = (const float*)d_in[1];
    const float* neg   = (const float*)d_in[2];
    const float* WQ  = (const float*)d_in[3];
    const float* bQ  = (const float*)d_in[4];
    const float* aQ  = (const float*)d_in[5];
    const float* gQ  = (const float*)d_in[6];
    const float* btQ = (const float*)d_in[7];
    const float* WK  = (const float*)d_in[8];
    const float* bK  = (const float*)d_in[9];
    const float* aK  = (const float*)d_in[10];
    const float* gK  = (const float*)d_in[11];
    const float* btK = (const float*)d_in[12];
    const float* WV  = (const float*)d_in[13];
    const float* bV  = (const float*)d_in[14];
    const float* aV  = (const float*)d_in[15];
    const float* gV  = (const float*)d_in[16];
    const float* btV = (const float*)d_in[17];
    const float* Wp  = (const float*)d_in[18];
    const float* bp  = (const float*)d_in[19];
    const float* ap  = (const float*)d_in[20];
    const float* gp  = (const float*)d_in[21];
    const float* btp = (const float*)d_in[22];
    float* out = (float*)d_out;

    void *pQf, *pKf, *pVfT, *pP, *pO;
    cudaGetSymbolAddress(&pQf, d_Qf);
    cudaGetSymbolAddress(&pKf, d_Kf);
    cudaGetSymbolAddress(&pVfT, d_VfT);
    cudaGetSymbolAddress(&pP, d_P);
    cudaGetSymbolAddress(&pO, d_O);

    const size_t smQK = (size_t)(C_ * F_ + 32  * 130) * sizeof(float);
    const size_t smVP = (size_t)(C_ * F_ + 128 * 130) * sizeof(float);
    const size_t smMMA = 2 * 4 * (128 * 40 * 2);   // 81,920 B
    cudaFuncSetAttribute(conv_ln_kernel<32, 8, 0, 4>,     cudaFuncAttributeMaxDynamicSharedMemorySize, (int)smQK);
    cudaFuncSetAttribute(conv_ln_kernel<32, 8, 1, 4>,     cudaFuncAttributeMaxDynamicSharedMemorySize, (int)smQK);
    cudaFuncSetAttribute(conv_ln_kernel<128, 32, 2, 8>,   cudaFuncAttributeMaxDynamicSharedMemorySize, (int)smVP);
    cudaFuncSetAttribute(conv_ln_kernel<128, 128, 3, 8>,  cudaFuncAttributeMaxDynamicSharedMemorySize, (int)smVP);
    cudaFuncSetAttribute(mma_gemm, cudaFuncAttributeMaxDynamicSharedMemorySize, (int)smMMA);

    {   // pooled signed cond
        int total = B_ * C_ * TC * F_;
        pool_kernel<<<(total + 255) / 256, 256>>>(pos, neg);
    }
    // Q / K / V branches
    conv_ln_kernel<32, 8, 0, 4><<<B_ * T_, 104, smQK>>>(batch, WQ, bQ, aQ, gQ, btQ, nullptr);
    conv_ln_kernel<32, 8, 1, 4><<<B_ * TC, 104, smQK>>>(nullptr, WK, bK, aK, gK, btK, nullptr);
    conv_ln_kernel<128, 32, 2, 8><<<B_ * TC, 208, smVP>>>(nullptr, WV, bV, aV, gV, btV, nullptr);
    {   // Vf -> VfT (K-major B operand for PV), zero-padded to 416
        dim3 g(DF / 32, PLD / 32, H_ * B_);
        transpose_v_kernel<<<g, dim3(32, 8)>>>();
    }
    {   // scores: P = Qf @ Kf^T (M=1000, N=398 -> pad 416, K=520, 17 chunks)
        dim3 g(4, 8, H_ * B_);
        mma_gemm<<<g, 256, smMMA>>>(
            (const float*)pQf, (const float*)pKf, (float*)pP,
            T_, TC, EF, 17, EF, EF, PLD,
            (long long)T_ * EF, (long long)TC * EF, (long long)T_ * PLD, PLD);
    }
    softmax_kernel<<<H_ * B_ * T_, 128>>>();
    {   // attention out: O = P @ VfT^T (M=1000, N=2080, K=416 padded, 13 chunks)
        dim3 g((DF + 127) / 128, 8, H_ * B_);
        mma_gemm<<<g, 256, smMMA>>>(
            (const float*)pP, (const float*)pVfT, (float*)pO,
            T_, DF, PLD, 13, PLD, PLD, DF,
            (long long)T_ * PLD, (long long)DF * PLD, (long long)T_ * DF, DF);
    }
    // concat projection + LN -> final output
    conv_ln_kernel<128, 128, 3, 8><<<B_ * T_, 208, smVP>>>(nullptr, Wp, bp, ap, gp, btp, out);
}

// round 8
// speedup vs baseline: 1.9798x; 1.2968x over previous
#include <cuda_runtime.h>
#include <cuda_bf16.h>
#include <math.h>
#include <stdint.h>

// ---------------- problem constants ----------------
namespace {
constexpr int B_ = 4, C_ = 128, T_ = 1000, F_ = 65;
constexpr int H_ = 4, E_ = 8, DH = 32;
constexpr int T1 = 199;          // pooled length per sign
constexpr int TC = 398;          // 2*T1
constexpr int EF = E_ * F_;      // 520
constexpr int DF = DH * F_;      // 2080
constexpr int PLD = 416;         // padded K-stride for P / VfT (13*32)
constexpr int NTFC = TC * F_;    // 25870  (cond spatial)
constexpr int NTFT = T_ * F_;    // 65000  (batch spatial)
constexpr float EPS = 1e-5f;
constexpr float QSCALE = 0.04385290096535146f;  // 1/sqrt(520)
}

// ---------------- scratch (__device__ globals; no-alloc rule) ----------------
__device__ __align__(16) float d_cond[(size_t)B_ * C_ * NTFC];     // [b,c,(tc,f)]
__device__ __align__(16) float d_XTc [(size_t)B_ * NTFC * C_];     // [b,(tc,f),c]
__device__ __align__(16) float d_Yk  [(size_t)B_ * 32 * NTFC];     // [b,oc,(tc,f)]
__device__ __align__(16) float d_Yv  [(size_t)B_ * 128 * NTFC];
__device__ __align__(16) float d_Qf  [(size_t)H_ * B_ * T_ * EF];  // [z, t, ef]
__device__ __align__(16) float d_Kf  [(size_t)H_ * B_ * TC * EF];
__device__ __align__(16) float d_Vf  [(size_t)H_ * B_ * TC * DF];
__device__ __align__(16) float d_VfT [(size_t)H_ * B_ * DF * PLD]; // [z, n, tc(pad0)]
__device__ __align__(16) float d_P   [(size_t)H_ * B_ * T_ * PLD];
__device__ __align__(16) float d_O   [(size_t)H_ * B_ * T_ * DF];  // [z, t, n]
__device__ __align__(16) float d_XTo [(size_t)B_ * NTFT * C_];     // [b,(t,f),c]
__device__ __align__(16) float d_Yp  [(size_t)B_ * 128 * NTFT];

// ---------------- helpers ----------------
__device__ __forceinline__ uint32_t smem_u32(const void* p) {
    uint32_t a;
    asm("{ .reg .u64 t; cvta.to.shared.u64 t, %1; cvt.u32.u64 %0, t; }" : "=r"(a) : "l"(p));
    return a;
}
__device__ __forceinline__ uint32_t pk2(float lo, float hi) {
    uint32_t r;
    asm("cvt.rn.bf16x2.f32 %0, %1, %2;" : "=r"(r) : "f"(hi), "f"(lo));
    return r;
}
__device__ __forceinline__ float bfhi(float x) {
    return __bfloat162float(__float2bfloat16(x));
}
__device__ __forceinline__ void ldsm4(uint32_t& r0, uint32_t& r1, uint32_t& r2, uint32_t& r3,
                                      uint32_t addr) {
    asm volatile("ldmatrix.sync.aligned.m8n8.x4.shared.b16 {%0,%1,%2,%3}, [%4];"
                 : "=r"(r0), "=r"(r1), "=r"(r2), "=r"(r3) : "r"(addr));
}
__device__ __forceinline__ void mma16816(float* c, const uint32_t* a, uint32_t b0, uint32_t b1) {
    asm volatile(
        "mma.sync.aligned.m16n8k16.row.col.f32.bf16.bf16.f32 "
        "{%0,%1,%2,%3}, {%4,%5,%6,%7}, {%8,%9}, {%0,%1,%2,%3};"
        : "+f"(c[0]), "+f"(c[1]), "+f"(c[2]), "+f"(c[3])
        : "r"(a[0]), "r"(a[1]), "r"(a[2]), "r"(a[3]), "r"(b0), "r"(b1));
}

// ---------------- 1) avg-pool along T + signed concat ----------------
__global__ void pool_kernel(const float* __restrict__ pos, const float* __restrict__ neg) {
    int idx = blockIdx.x * blockDim.x + threadIdx.x;
    constexpr int total = B_ * C_ * TC * F_;
    if (idx >= total) return;
    int f  = idx % F_;
    int r  = idx / F_;
    int tc = r % TC;  r /= TC;
    int c  = r % C_;
    int b  = r / C_;
    const float* src; float sg; int t0;
    if (tc < T1) { src = pos; sg =  0.1f; t0 = tc * 5; }
    else         { src = neg; sg = -0.1f; t0 = (tc - T1) * 5; }
    const float* p = src + ((size_t)(b * C_ + c) * T_ + t0) * F_ + f;
    float s = 0.f;
#pragma unroll
    for (int k = 0; k < 10; k++) s += p[(size_t)k * F_];
    d_cond[idx] = s * sg;
}

// ---------------- 2) Q branch: conv1x1 + PReLU + LN (fp32, small OC) ----------------
__global__ void __launch_bounds__(104)
conv_ln_q(const float* __restrict__ xin, const float* __restrict__ W,
          const float* __restrict__ bias, const float* __restrict__ alpha,
          const float* __restrict__ gamma, const float* __restrict__ beta) {
    constexpr int OC = 32, GRP = 8, WS = 130, NTHR = 104;
    extern __shared__ float sm[];
    float* xs = sm;                        // C_*F_
    float* ws = sm + C_ * F_;              // OC*WS
    __shared__ float s_sum[OC / GRP], s_sq[OC / GRP];

    int bid = blockIdx.x;
    int b = bid / T_, t = bid % T_;
    int tid = threadIdx.x;

    for (int i = tid; i < C_ * F_; i += NTHR) {
        int c = i / F_, f = i - c * F_;
        xs[i] = xin[((size_t)(b * C_ + c) * T_ + t) * F_ + f];
    }
    for (int i = tid; i < OC * C_; i += NTHR) ws[(i >> 7) * WS + (i & 127)] = W[i];
    if (tid < OC / GRP) { s_sum[tid] = 0.f; s_sq[tid] = 0.f; }
    __syncthreads();

    int ocg = tid / 13, fg = tid - ocg * 13;
    int oc0 = ocg * 4, f0 = fg * 5;

    float acc[4][5];
#pragma unroll
    for (int i = 0; i < 4; i++) {
        float bv = bias[oc0 + i];
#pragma unroll
        for (int j = 0; j < 5; j++) acc[i][j] = bv;
    }
    for (int c = 0; c < C_; c++) {
        float xv[5];
#pragma unroll
        for (int j = 0; j < 5; j++) xv[j] = xs[c * F_ + f0 + j];
#pragma unroll
        for (int i = 0; i < 4; i++) {
            float wv = ws[(oc0 + i) * WS + c];
#pragma unroll
            for (int j = 0; j < 5; j++) acc[i][j] = fmaf(wv, xv[j], acc[i][j]);
        }
    }

    int g = oc0 / GRP;
    float a = alpha[g];
    float ps = 0.f, pq = 0.f;
#pragma unroll
    for (int i = 0; i < 4; i++)
#pragma unroll
        for (int j = 0; j < 5; j++) {
            float v = acc[i][j];
            v = (v >= 0.f) ? v : a * v;
            acc[i][j] = v;
            ps += v; pq += v * v;
        }
    atomicAdd(&s_sum[g], ps);
    atomicAdd(&s_sq[g], pq);
    __syncthreads();

    const float invn = 1.f / (float)(GRP * F_);
    float mu  = s_sum[g] * invn;
    float var = s_sq[g] * invn - mu * mu;
    float rinv = rsqrtf(var + EPS);

#pragma unroll
    for (int i = 0; i < 4; i++) {
        int oc = oc0 + i;
#pragma unroll
        for (int j = 0; j < 5; j++) {
            int f = f0 + j;
            float v = (acc[i][j] - mu) * rinv * gamma[oc * F_ + f] + beta[oc * F_ + f];
            d_Qf[((size_t)((oc >> 3) * B_ + b) * T_ + t) * EF + (oc & 7) * F_ + f] = v * QSCALE;
        }
    }
}

// ---------------- 3) transpose d_cond [b][c][ntf] -> d_XTc [b][ntf][c] ----------------
__global__ void transpose_cf_kernel() {
    __shared__ float tl[32][33];
    int b = blockIdx.z;
    int c0 = blockIdx.y * 32, n0 = blockIdx.x * 32;
    int tx = threadIdx.x, ty = threadIdx.y;   // (32, 8)
#pragma unroll
    for (int i = ty; i < 32; i += 8) {
        int c = c0 + i, n = n0 + tx;
        float v = 0.f;
        if (n < NTFC) v = d_cond[((size_t)b * C_ + c) * NTFC + n];
        tl[i][tx] = v;
    }
    __syncthreads();
#pragma unroll
    for (int i = ty; i < 32; i += 8) {
        int n = n0 + i;
        if (n < NTFC) d_XTc[((size_t)b * NTFC + n) * C_ + c0 + tx] = tl[tx][i];
    }
}

// ---------------- 4) shuffle d_O [z=(h,b)][t][dh*65+f] -> d_XTo [b][(t,f)][h*32+dh] ------
__global__ void __launch_bounds__(256) shuffle_o_kernel() {
    __shared__ float so[4 * DF];           // 33 KB
    int bid = blockIdx.x;
    int b = bid / T_, t = bid % T_;
    int tid = threadIdx.x;
    for (int i = tid; i < 4 * DF; i += 256) {
        int h = i / DF, rem = i - h * DF;
        so[i] = d_O[((size_t)(h * B_ + b) * T_ + t) * DF + rem];
    }
    __syncthreads();
    float* dst = d_XTo + ((size_t)b * NTFT + (size_t)t * F_) * C_;
    for (int i = tid; i < F_ * C_; i += 256) {
        int c = i & 127, f = i >> 7;
        int h = c >> 5, dh = c & 31;
        dst[(size_t)f * C_ + c] = so[h * DF + dh * F_ + f];
    }
}

// ---------------- 5) bf16-split tensor-core GEMM: C[M,N] = A[M,K] * B[N,K]^T ----------------
// 3x bf16 passes (hi*hi + hi*lo + lo*hi), fp32 accumulate. BM=BN=128, BK=32.
__global__ void __launch_bounds__(256)
mma_gemm(const float* __restrict__ A, const float* __restrict__ B, float* __restrict__ C,
         int M, int NrowsB, int Kvalid, int Kchunks,
         int lda, int ldb, int ldc,
         long long sAz, long long sBz, long long sCz, int writeN) {
    extern __shared__ __align__(16) char smc[];
    uint32_t sb = smem_u32(smc);
    constexpr uint32_t TSB = 128u * 40u * 2u;           // 10240 B per tile

    int tid = threadIdx.x, lane = tid & 31, wid = tid >> 5;
    int wm = wid & 3, wn = wid >> 2;
    int z = blockIdx.z;
    const float* Az = A + sAz * z;
    const float* Bz = B + sBz * z;
    float* Cz = C + sCz * z;
    int mBase = blockIdx.y * 128, nBase = blockIdx.x * 128;

    float acc[2][8][4];
#pragma unroll
    for (int i = 0; i < 2; i++)
#pragma unroll
        for (int j = 0; j < 8; j++)
#pragma unroll
            for (int k = 0; k < 4; k++) acc[i][j][k] = 0.f;

    const float4 f4z = make_float4(0.f, 0.f, 0.f, 0.f);
    float4 ra[4], rb[4];

    auto ldg = [&](int c) {
        int k0 = c * 32;
#pragma unroll
        for (int i = 0; i < 4; i++) {
            int idx = i * 256 + tid;
            int r = idx >> 3, gk = k0 + ((idx & 7) << 2);
            int gra = mBase + r;
            ra[i] = (gra < M && gk < Kvalid) ? *(const float4*)(Az + (size_t)gra * lda + gk) : f4z;
            int grb = nBase + r;
            rb[i] = (grb < NrowsB && gk < Kvalid) ? *(const float4*)(Bz + (size_t)grb * ldb + gk) : f4z;
        }
    };
    auto sts = [&](int s) {
        char* st = smc + (size_t)s * 4 * TSB;
#pragma unroll
        for (int i = 0; i < 4; i++) {
            int idx = i * 256 + tid;
            int r = idx >> 3, k = (idx & 7) << 2;
            uint32_t off = (uint32_t)(r * 80 + k * 2);
            float4 v = ra[i];
            float hx = bfhi(v.x), hy = bfhi(v.y), hz = bfhi(v.z), hw = bfhi(v.w);
            uint2 Hc = make_uint2(pk2(hx, hy), pk2(hz, hw));
            uint2 Lc = make_uint2(pk2(v.x - hx, v.y - hy), pk2(v.z - hz, v.w - hw));
            *(uint2*)(st + off)        = Hc;
            *(uint2*)(st + TSB + off)  = Lc;
            v = rb[i];
            hx = bfhi(v.x); hy = bfhi(v.y); hz = bfhi(v.z); hw = bfhi(v.w);
            Hc = make_uint2(pk2(hx, hy), pk2(hz, hw));
            Lc = make_uint2(pk2(v.x - hx, v.y - hy), pk2(v.z - hz, v.w - hw));
            *(uint2*)(st + 2 * TSB + off) = Hc;
            *(uint2*)(st + 3 * TSB + off) = Lc;
        }
    };

    uint32_t aRow = (uint32_t)((wm * 32 + (lane & 15)) * 80 + ((lane >> 4) << 4));
    uint32_t bRow = (uint32_t)((wn * 64 + (lane & 15)) * 80 + ((lane >> 4) << 4));

    auto compute = [&](int s) {
        uint32_t st = sb + (uint32_t)s * 4 * TSB;
#pragma unroll
        for (int ks = 0; ks < 2; ks++) {
            uint32_t ah[2][4], al[2][4];
#pragma unroll
            for (int mi = 0; mi < 2; mi++) {
                uint32_t ad = st + aRow + (uint32_t)(mi * 1280 + ks * 32);
                ldsm4(ah[mi][0], ah[mi][1], ah[mi][2], ah[mi][3], ad);
                ldsm4(al[mi][0], al[mi][1], al[mi][2], al[mi][3], ad + TSB);
            }
#pragma unroll
            for (int j = 0; j < 4; j++) {
                uint32_t bd = st + 2 * TSB + bRow + (uint32_t)(j * 1280 + ks * 32);
                uint32_t h0, h1, h2, h3, l0, l1, l2, l3;
                ldsm4(h0, h1, h2, h3, bd);
                ldsm4(l0, l1, l2, l3, bd + TSB);
                // pass-major order: 4 independent accumulators per pass (gap 4)
                mma16816(acc[0][2 * j],     ah[0], h0, h2);
                mma16816(acc[1][2 * j],     ah[1], h0, h2);
                mma16816(acc[0][2 * j + 1], ah[0], h1, h3);
                mma16816(acc[1][2 * j + 1], ah[1], h1, h3);
                mma16816(acc[0][2 * j],     ah[0], l0, l2);
                mma16816(acc[1][2 * j],     ah[1], l0, l2);
                mma16816(acc[0][2 * j + 1], ah[0], l1, l3);
                mma16816(acc[1][2 * j + 1], ah[1], l1, l3);
                mma16816(acc[0][2 * j],     al[0], h0, h2);
                mma16816(acc[1][2 * j],     al[1], h0, h2);
                mma16816(acc[0][2 * j + 1], al[0], h1, h3);
                mma16816(acc[1][2 * j + 1], al[1], h1, h3);
            }
        }
    };

    ldg(0);
    sts(0);
    __syncthreads();
    for (int c = 0; c < Kchunks; c++) {
        bool nxt = (c + 1 < Kchunks);
        if (nxt) ldg(c + 1);
        compute(c & 1);
        if (nxt) {
            sts((c + 1) & 1);
            __syncthreads();
        }
    }

    // epilogue
#pragma unroll
    for (int mi = 0; mi < 2; mi++) {
#pragma unroll
        for (int ni = 0; ni < 8; ni++) {
            int r0 = mBase + wm * 32 + mi * 16 + (lane >> 2);
            int col = nBase + wn * 64 + ni * 8 + ((lane & 3) << 1);
            if (col < writeN) {
                if (r0 < M) {
                    float2 v = make_float2(acc[mi][ni][0], acc[mi][ni][1]);
                    *(float2*)(Cz + (size_t)r0 * ldc + col) = v;
                }
                if (r0 + 8 < M) {
                    float2 v = make_float2(acc[mi][ni][2], acc[mi][ni][3]);
                    *(float2*)(Cz + (size_t)(r0 + 8) * ldc + col) = v;
                }
            }
        }
    }
}

// ---------------- 6) fused bias + PReLU + LN epilogue after conv GEMMs ----------------
// MODE: 1=K -> d_Kf   2=V -> d_Vf   3=proj -> out
template <int OC, int NG, int MODE>
__global__ void __launch_bounds__(256)
ln_kernel(const float* __restrict__ Y, int ldn,
          const float* __restrict__ bias, const float* __restrict__ alpha,
          const float* __restrict__ gamma, const float* __restrict__ beta,
          float* __restrict__ outp) {
    constexpr int GR = OC / NG;            // rows per group
    constexpr int NEL = GR * F_;           // elements per group
    constexpr int TPG = 256 / NG;          // threads per group
    constexpr int Tx = (MODE == 3) ? T_ : TC;
    __shared__ float buf[OC * F_];
    __shared__ float s_sum[NG], s_sq[NG];

    int bid = blockIdx.x;
    int b = bid / Tx, t = bid % Tx;
    int tid = threadIdx.x;
    int g = tid / TPG, l = tid - g * TPG;

    if (tid < NG) { s_sum[tid] = 0.f; s_sq[tid] = 0.f; }
    __syncthreads();

    const float* Yb = Y + ((size_t)b * OC) * ldn + (size_t)t * F_;
    float a = alpha[(MODE == 3) ? 0 : g];
    float s = 0.f, q = 0.f;
    for (int j = l; j < NEL; j += TPG) {
        int r = j / F_, f = j - r * F_;
        int row = g * GR + r;
        float v = Yb[(size_t)row * ldn + f] + bias[row];
        v = (v >= 0.f) ? v : a * v;
        buf[g * NEL + j] = v;
        s += v; q += v * v;
    }
#pragma unroll
    for (int o = 16; o > 0; o >>= 1) {
        s += __shfl_xor_sync(0xffffffffu, s, o);
        q += __shfl_xor_sync(0xffffffffu, q, o);
    }
    if ((tid & 31) == 0) { atomicAdd(&s_sum[g], s); atomicAdd(&s_sq[g], q); }
    __syncthreads();

    const float invn = 1.f / (float)NEL;
    float mu = s_sum[g] * invn;
    float var = s_sq[g] * invn - mu * mu;
    float rinv = rsqrtf(var + EPS);

    for (int j = l; j < NEL; j += TPG) {
        float v = (buf[g * NEL + j] - mu) * rinv * gamma[g * NEL + j] + beta[g * NEL + j];
        if (MODE == 1) {
            d_Kf[((size_t)(g * B_ + b) * TC + t) * EF + j] = v;
        } else if (MODE == 2) {
            d_Vf[((size_t)(g * B_ + b) * TC + t) * DF + j] = v;
        } else {
            int r = j / F_, f = j - r * F_;
            outp[((size_t)(b * C_ + r) * T_ + t) * F_ + f] = v;
        }
    }
}

// ---------------- 7) transpose Vf [z,tc,n] -> VfT [z,n,tc(pad 416, zeros)] ----------------
__global__ void transpose_v_kernel() {
    __shared__ float tile[32][33];
    int z = blockIdx.z;
    int n0 = blockIdx.x * 32, t0 = blockIdx.y * 32;
    int tx = threadIdx.x, ty = threadIdx.y;   // (32, 8)
#pragma unroll
    for (int i = ty; i < 32; i += 8) {
        int t = t0 + i, n = n0 + tx;
        float v = 0.f;
        if (t < TC && n < DF) v = d_Vf[((size_t)z * TC + t) * DF + n];
        tile[i][tx] = v;
    }
    __syncthreads();
#pragma unroll
    for (int i = ty; i < 32; i += 8) {
        int n = n0 + i, t = t0 + tx;
        if (n < DF) d_VfT[((size_t)z * DF + n) * PLD + t] = tile[tx][i];
    }
}

// ---------------- 8) softmax over tc (len 398), in place on d_P (ld 416) ----------------
__global__ void __launch_bounds__(128) softmax_kernel() {
    size_t row = blockIdx.x;
    float* p = d_P + row * PLD;
    int tid = threadIdx.x;
    float v[4];
    int cnt = 0;
    float mx = -3.4e38f;
    for (int i = tid; i < TC; i += 128) { float x = p[i]; v[cnt++] = x; mx = fmaxf(mx, x); }
    __shared__ float smax[4], ssum[4];
#pragma unroll
    for (int o = 16; o > 0; o >>= 1) mx = fmaxf(mx, __shfl_xor_sync(0xffffffffu, mx, o));
    if ((tid & 31) == 0) smax[tid >> 5] = mx;
    __syncthreads();
    mx = fmaxf(fmaxf(smax[0], smax[1]), fmaxf(smax[2], smax[3]));
    float s = 0.f;
    for (int k = 0; k < cnt; k++) { float e = __expf(v[k] - mx); v[k] = e; s += e; }
#pragma unroll
    for (int o = 16; o > 0; o >>= 1) s += __shfl_xor_sync(0xffffffffu, s, o);
    if ((tid & 31) == 0) ssum[tid >> 5] = s;
    __syncthreads();
    s = ssum[0] + ssum[1] + ssum[2] + ssum[3];
    float inv = 1.f / s;
    cnt = 0;
    for (int i = tid; i < TC; i += 128) p[i] = v[cnt++] * inv;
}

// ---------------- launch ----------------
extern "C" void kernel_launch(void* const* d_in, const int* in_sizes, int n_in,
                              void* d_out, int out_size) {
    (void)in_sizes; (void)n_in; (void)out_size;
    const float* batch = (const float*)d_in[0];
    const float* pos   = (const float*)d_in[1];
    const float* neg   = (const float*)d_in[2];
    const float* WQ  = (const float*)d_in[3];
    const float* bQ  = (const float*)d_in[4];
    const float* aQ  = (const float*)d_in[5];
    const float* gQ  = (const float*)d_in[6];
    const float* btQ = (const float*)d_in[7];
    const float* WK  = (const float*)d_in[8];
    const float* bK  = (const float*)d_in[9];
    const float* aK  = (const float*)d_in[10];
    const float* gK  = (const float*)d_in[11];
    const float* btK = (const float*)d_in[12];
    const float* WV  = (const float*)d_in[13];
    const float* bV  = (const float*)d_in[14];
    const float* aV  = (const float*)d_in[15];
    const float* gV  = (const float*)d_in[16];
    const float* btV = (const float*)d_in[17];
    const float* Wp  = (const float*)d_in[18];
    const float* bp  = (const float*)d_in[19];
    const float* ap  = (const float*)d_in[20];
    const float* gp  = (const float*)d_in[21];
    const float* btp = (const float*)d_in[22];
    float* out = (float*)d_out;

    void *pQf, *pKf, *pVfT, *pP, *pO, *pXTc, *pXTo, *pYk, *pYv, *pYp;
    cudaGetSymbolAddress(&pQf, d_Qf);
    cudaGetSymbolAddress(&pKf, d_Kf);
    cudaGetSymbolAddress(&pVfT, d_VfT);
    cudaGetSymbolAddress(&pP, d_P);
    cudaGetSymbolAddress(&pO, d_O);
    cudaGetSymbolAddress(&pXTc, d_XTc);
    cudaGetSymbolAddress(&pXTo, d_XTo);
    cudaGetSymbolAddress(&pYk, d_Yk);
    cudaGetSymbolAddress(&pYv, d_Yv);
    cudaGetSymbolAddress(&pYp, d_Yp);

    const size_t smQK = (size_t)(C_ * F_ + 32 * 130) * sizeof(float);
    const size_t smMMA = 2 * 4 * (128 * 40 * 2);   // 81,920 B
    cudaFuncSetAttribute(conv_ln_q, cudaFuncAttributeMaxDynamicSharedMemorySize, (int)smQK);
    cudaFuncSetAttribute(mma_gemm, cudaFuncAttributeMaxDynamicSharedMemorySize, (int)smMMA);

    {   // pooled signed cond
        int total = B_ * C_ * TC * F_;
        pool_kernel<<<(total + 255) / 256, 256>>>(pos, neg);
    }
    // Q branch (fp32 conv+LN fused, writes d_Qf with QSCALE folded)
    conv_ln_q<<<B_ * T_, 104, smQK>>>(batch, WQ, bQ, aQ, gQ, btQ);

    {   // cond -> K-major layout for conv GEMMs
        dim3 g((NTFC + 31) / 32, C_ / 32, B_);
        transpose_cf_kernel<<<g, dim3(32, 8)>>>();
    }
    {   // K conv GEMM: Yk[b][oc<32][ntf] = WK @ XTc^T
        dim3 g((NTFC + 127) / 128, 1, B_);
        mma_gemm<<<g, 256, smMMA>>>(WK, (const float*)pXTc, (float*)pYk,
            32, NTFC, C_, 4, C_, C_, NTFC,
            0LL, (long long)NTFC * C_, (long long)32 * NTFC, NTFC);
    }
    {   // V conv GEMM: Yv[b][oc<128][ntf] = WV @ XTc^T
        dim3 g((NTFC + 127) / 128, 1, B_);
        mma_gemm<<<g, 256, smMMA>>>(WV, (const float*)pXTc, (float*)pYv,
            128, NTFC, C_, 4, C_, C_, NTFC,
            0LL, (long long)NTFC * C_, (long long)128 * NTFC, NTFC);
    }
    // K / V epilogues: bias + PReLU + LN -> Kf / Vf
    ln_kernel<32, 4, 1><<<B_ * TC, 256>>>((const float*)pYk, NTFC, bK, aK, gK, btK, nullptr);
    ln_kernel<128, 4, 2><<<B_ * TC, 256>>>((const float*)pYv, NTFC, bV, aV, gV, btV, nullptr);
    {   // Vf -> VfT (K-major B operand for PV), zero-padded to 416
        dim3 g(DF / 32, PLD / 32, H_ * B_);
        transpose_v_kernel<<<g, dim3(32, 8)>>>();
    }
    {   // scores: P = Qf @ Kf^T (M=1000, N=398 -> pad 416, K=520, 17 chunks)
        dim3 g(4, 8, H_ * B_);
        mma_gemm<<<g, 256, smMMA>>>(
            (const float*)pQf, (const float*)pKf, (float*)pP,
            T_, TC, EF, 17, EF, EF, PLD,
            (long long)T_ * EF, (long long)TC * EF, (long long)T_ * PLD, PLD);
    }
    softmax_kernel<<<H_ * B_ * T_, 128>>>();
    {   // attention out: O = P @ VfT^T (M=1000, N=2080, K=416 padded, 13 chunks)
        dim3 g((DF + 127) / 128, 8, H_ * B_);
        mma_gemm<<<g, 256, smMMA>>>(
            (const float*)pP, (const float*)pVfT, (float*)pO,
            T_, DF, PLD, 13, PLD, PLD, DF,
            (long long)T_ * PLD, (long long)DF * PLD, (long long)T_ * DF, DF);
    }
    // O -> K-major layout for proj GEMM
    shuffle_o_kernel<<<B_ * T_, 256>>>();
    {   // proj GEMM: Yp[b][e][ntf] = Wp @ XTo^T
        dim3 g((NTFT + 127) / 128, 1, B_);
        mma_gemm<<<g, 256, smMMA>>>(Wp, (const float*)pXTo, (float*)pYp,
            128, NTFT, C_, 4, C_, C_, NTFT,
            0LL, (long long)NTFT * C_, (long long)128 * NTFT, NTFT);
    }
    // proj epilogue: bias + PReLU + LN -> final output
    ln_kernel<128, 1, 3><<<B_ * T_, 256>>>((const float*)pYp, NTFT, bp, ap, gp, btp, out);
}